// round 5
// baseline (speedup 1.0000x reference)
#include <cuda_runtime.h>
#include <math.h>

#define NNODES 50000
#define NEDGES 800000

// ---------------- scratch (device globals: allocation-free) ----------------
__device__ int   g_cnt[NNODES];
__device__ int   g_cursor[NNODES];
__device__ int   g_rowptr[NNODES + 1];
__device__ int   g_colp[NEDGES];
__device__ float g_simp[NEDGES];   // after sim_fused: edge weight exp(att) (0 if dropped)
__device__ float g_invn[NNODES];
__device__ float g_wself[NNODES];
__device__ float g_z [NNODES * 256];
__device__ float g_h1[NNODES * 256];
__device__ float g_h2[NNODES * 256];
__device__ float g_B [256 * 256];

// ---------------- CSR build ----------------
__global__ void zero_cnt_kernel() {
    int i = blockIdx.x * blockDim.x + threadIdx.x;
    if (i < NNODES) g_cnt[i] = 0;
}

__global__ void hist_kernel(const int* __restrict__ row) {
    int e = blockIdx.x * blockDim.x + threadIdx.x;
    if (e < NEDGES) atomicAdd(&g_cnt[row[e]], 1);
}

__global__ void scan_kernel() {
    __shared__ int wsum[32];
    __shared__ int carry;
    int tid = threadIdx.x, lane = tid & 31, wid = tid >> 5;
    if (tid == 0) { carry = 0; g_rowptr[0] = 0; }
    __syncthreads();
    for (int base = 0; base < NNODES; base += 1024) {
        int i = base + tid;
        int v = (i < NNODES) ? g_cnt[i] : 0;
        int s = v;
        #pragma unroll
        for (int o = 1; o < 32; o <<= 1) {
            int t = __shfl_up_sync(0xffffffffu, s, o);
            if (lane >= o) s += t;
        }
        if (lane == 31) wsum[wid] = s;
        __syncthreads();
        if (wid == 0) {
            int ws = wsum[lane];
            #pragma unroll
            for (int o = 1; o < 32; o <<= 1) {
                int t = __shfl_up_sync(0xffffffffu, ws, o);
                if (lane >= o) ws += t;
            }
            wsum[lane] = ws;
        }
        __syncthreads();
        int incl = s + (wid ? wsum[wid - 1] : 0) + carry;
        if (i < NNODES) { g_rowptr[i + 1] = incl; g_cursor[i] = incl - v; }
        __syncthreads();
        if (tid == 1023) carry = incl;
        __syncthreads();
    }
}

__global__ void scatter_kernel(const int* __restrict__ row, const int* __restrict__ col) {
    int e = blockIdx.x * blockDim.x + threadIdx.x;
    if (e >= NEDGES) return;
    int r = row[e];
    int pos = atomicAdd(&g_cursor[r], 1);
    g_colp[pos] = col[e];
}

// ---------------- per-layer kernels ----------------
// repack W[h, d, o] -> B[d, h*HID+o]  (dense [D x Hout] row-major)
__global__ void repack_kernel(const float* __restrict__ W, int D, int Hout, int HIDp) {
    int idx = blockIdx.x * blockDim.x + threadIdx.x;
    if (idx >= D * Hout) return;
    int d = idx / Hout, c = idx % Hout;
    int h = c / HIDp, o = c % HIDp;
    g_B[idx] = W[((size_t)h * D + d) * HIDp + o];
}

// 1 / max(||x_n||, 1e-12), warp per node
__global__ void invn_kernel(const float* __restrict__ x, int D) {
    int n = (blockIdx.x * blockDim.x + threadIdx.x) >> 5;
    int lane = threadIdx.x & 31;
    if (n >= NNODES) return;
    const float4* xr = (const float4*)(x + (size_t)n * D);
    int nq = D >> 2;
    float s = 0.f;
    for (int j = lane; j < nq; j += 32) {
        float4 a = xr[j];
        s += a.x * a.x + a.y * a.y + a.z * a.z + a.w * a.w;
    }
    #pragma unroll
    for (int o = 16; o; o >>= 1) s += __shfl_xor_sync(0xffffffffu, s, o);
    if (lane == 0) g_invn[n] = 1.f / fmaxf(sqrtf(s), 1e-12f);
}

// fused: thresholded cosine sim + L1 row-normalization + degree self-weight +
// final edge weight exp(att). Warp per node; row features stay in registers.
// After this kernel: g_simp[i] = exp(sim_i / rowsum) for surviving edges else 0,
// g_wself[n] = exp(1/(deg+1)).
__global__ void sim_fused_kernel(const float* __restrict__ x, int D) {
    int n = (blockIdx.x * blockDim.x + threadIdx.x) >> 5;
    int lane = threadIdx.x & 31;
    if (n >= NNODES) return;
    const float4* xr = (const float4*)(x + (size_t)n * D);
    float4 r0 = xr[lane];
    float4 r1 = make_float4(0.f, 0.f, 0.f, 0.f);
    if (D == 256) r1 = xr[32 + lane];
    float invn_n = g_invn[n];
    int e0 = g_rowptr[n], e1 = g_rowptr[n + 1];
    float sum = 0.f;
    int cnt = 0;
    for (int i = e0; i < e1; ++i) {
        int c = g_colp[i];
        const float4* xc = (const float4*)(x + (size_t)c * D);
        float4 b0 = xc[lane];
        float s = r0.x * b0.x + r0.y * b0.y + r0.z * b0.z + r0.w * b0.w;
        if (D == 256) {
            float4 b1 = xc[32 + lane];
            s += r1.x * b1.x + r1.y * b1.y + r1.z * b1.z + r1.w * b1.w;
        }
        #pragma unroll
        for (int o = 16; o; o >>= 1) s += __shfl_xor_sync(0xffffffffu, s, o);
        // all lanes hold the full dot after the butterfly
        s *= invn_n * g_invn[c];
        float sv = (s < 0.1f) ? 0.f : s;
        if (lane == 0) g_simp[i] = sv;
        sum += sv;                 // sv >= 0, |sv| == sv; identical on all lanes
        cnt += (sv != 0.f);
    }
    float invrs = (sum > 0.f) ? 1.f / sum : 0.f;
    if (lane == 0) g_wself[n] = expf(1.f / ((float)cnt + 1.f));
    __syncwarp();
    for (int i = e0 + lane; i < e1; i += 32) {
        float sv = g_simp[i];
        g_simp[i] = (sv == 0.f) ? 0.f : expf(sv * invrs);
    }
}

// ---------------- 3xTF32 tensor-core GEMM (fp32-accurate) ----------------
__device__ __forceinline__ unsigned f2tf32(float f) {
    unsigned r;
    asm("cvt.rna.tf32.f32 %0, %1;" : "=r"(r) : "f"(f));
    return r;
}

__device__ __forceinline__ void mma_tf32(float c[4], unsigned a0, unsigned a1,
                                         unsigned a2, unsigned a3,
                                         unsigned b0, unsigned b1) {
    asm volatile(
        "mma.sync.aligned.m16n8k8.row.col.f32.tf32.tf32.f32 "
        "{%0,%1,%2,%3}, {%4,%5,%6,%7}, {%8,%9}, {%0,%1,%2,%3};"
        : "+f"(c[0]), "+f"(c[1]), "+f"(c[2]), "+f"(c[3])
        : "r"(a0), "r"(a1), "r"(a2), "r"(a3), "r"(b0), "r"(b1));
}

// C[M, Nc] = A[M, K] * B[K, Nc], BM=128 BN=64 BK=16, 8 warps (warp tile 32x32)
__global__ void __launch_bounds__(256)
mma_gemm_kernel(const float* __restrict__ A, const float* __restrict__ Bw,
                float* __restrict__ C, int M, int K, int Nc) {
    __shared__ unsigned AsHi[128][20];
    __shared__ unsigned AsLo[128][20];
    __shared__ unsigned BsHi[16][68];
    __shared__ unsigned BsLo[16][68];

    int tid = threadIdx.x;
    int lane = tid & 31, w = tid >> 5;
    int wm = w & 3, wn = w >> 2;       // 4 warps in M, 2 in N
    int g = lane >> 2, t = lane & 3;
    int rb = blockIdx.y * 128, cb = blockIdx.x * 64;

    float acc[2][4][4];
    #pragma unroll
    for (int mi = 0; mi < 2; mi++)
        #pragma unroll
        for (int ni = 0; ni < 4; ni++)
            #pragma unroll
            for (int j = 0; j < 4; j++) acc[mi][ni][j] = 0.f;

    for (int k0 = 0; k0 < K; k0 += 16) {
        // A tile 128x16 -> 512 float4, 2 per thread
        #pragma unroll
        for (int f = tid; f < 512; f += 256) {
            int r = f >> 2, kq = f & 3;
            int gr = rb + r;
            float4 v = make_float4(0.f, 0.f, 0.f, 0.f);
            if (gr < M) v = *(const float4*)&A[(size_t)gr * K + k0 + kq * 4];
            float vv[4] = {v.x, v.y, v.z, v.w};
            #pragma unroll
            for (int j = 0; j < 4; j++) {
                unsigned hi = f2tf32(vv[j]);
                AsHi[r][kq * 4 + j] = hi;
                AsLo[r][kq * 4 + j] = f2tf32(vv[j] - __uint_as_float(hi));
            }
        }
        // B tile 16x64 -> 256 float4, 1 per thread
        {
            int r = tid >> 4, nq = tid & 15;
            float4 v = *(const float4*)&Bw[(size_t)(k0 + r) * Nc + cb + nq * 4];
            float vv[4] = {v.x, v.y, v.z, v.w};
            #pragma unroll
            for (int j = 0; j < 4; j++) {
                unsigned hi = f2tf32(vv[j]);
                BsHi[r][nq * 4 + j] = hi;
                BsLo[r][nq * 4 + j] = f2tf32(vv[j] - __uint_as_float(hi));
            }
        }
        __syncthreads();

        #pragma unroll
        for (int kk = 0; kk < 16; kk += 8) {
            unsigned ah[2][4], al[2][4], bh[4][2], bl[4][2];
            #pragma unroll
            for (int mi = 0; mi < 2; mi++) {
                int r0 = wm * 32 + mi * 16 + g;
                ah[mi][0] = AsHi[r0][kk + t];     ah[mi][1] = AsHi[r0 + 8][kk + t];
                ah[mi][2] = AsHi[r0][kk + t + 4]; ah[mi][3] = AsHi[r0 + 8][kk + t + 4];
                al[mi][0] = AsLo[r0][kk + t];     al[mi][1] = AsLo[r0 + 8][kk + t];
                al[mi][2] = AsLo[r0][kk + t + 4]; al[mi][3] = AsLo[r0 + 8][kk + t + 4];
            }
            #pragma unroll
            for (int ni = 0; ni < 4; ni++) {
                int c0 = wn * 32 + ni * 8 + g;
                bh[ni][0] = BsHi[kk + t][c0]; bh[ni][1] = BsHi[kk + t + 4][c0];
                bl[ni][0] = BsLo[kk + t][c0]; bl[ni][1] = BsLo[kk + t + 4][c0];
            }
            #pragma unroll
            for (int mi = 0; mi < 2; mi++)
                #pragma unroll
                for (int ni = 0; ni < 4; ni++) {
                    // 3xTF32: hi*hi + hi*lo + lo*hi ~= fp32 product
                    mma_tf32(acc[mi][ni], ah[mi][0], ah[mi][1], ah[mi][2], ah[mi][3],
                             bh[ni][0], bh[ni][1]);
                    mma_tf32(acc[mi][ni], ah[mi][0], ah[mi][1], ah[mi][2], ah[mi][3],
                             bl[ni][0], bl[ni][1]);
                    mma_tf32(acc[mi][ni], al[mi][0], al[mi][1], al[mi][2], al[mi][3],
                             bh[ni][0], bh[ni][1]);
                }
        }
        __syncthreads();
    }

    #pragma unroll
    for (int mi = 0; mi < 2; mi++) {
        int row = rb + wm * 32 + mi * 16 + g;
        #pragma unroll
        for (int ni = 0; ni < 4; ni++) {
            int colc = cb + wn * 32 + ni * 8 + 2 * t;
            if (row < M)
                *(float2*)&C[(size_t)row * Nc + colc] =
                    make_float2(acc[mi][ni][0], acc[mi][ni][1]);
            if (row + 8 < M)
                *(float2*)&C[(size_t)(row + 8) * Nc + colc] =
                    make_float2(acc[mi][ni][2], acc[mi][ni][3]);
        }
    }
}

// plain tiled SGEMM (kept for the tiny N=16 final projection)
template <int BM, int BN, int BK, int TM, int TN>
__global__ void __launch_bounds__(256)
sgemm_kernel(const float* __restrict__ A, const float* __restrict__ Bw,
             float* __restrict__ C, int M, int K, int Nc) {
    static_assert((BM / TM) * (BN / TN) == 256, "grid of 256 threads");
    __shared__ float As[BK][BM + 4];
    __shared__ float Bs[BK][BN];
    constexpr int TCOLS = BN / TN;
    int tid = threadIdx.x;
    int tr = tid / TCOLS, tc = tid % TCOLS;
    int rb = blockIdx.y * BM, cb = blockIdx.x * BN;
    float acc[TM][TN];
    #pragma unroll
    for (int i = 0; i < TM; i++)
        #pragma unroll
        for (int j = 0; j < TN; j++) acc[i][j] = 0.f;

    for (int k0 = 0; k0 < K; k0 += BK) {
        for (int idx = tid; idx < BM * BK; idx += 256) {
            int r = idx / BK, c = idx % BK;
            int gr = rb + r;
            As[c][r] = (gr < M) ? A[(size_t)gr * K + k0 + c] : 0.f;
        }
        for (int idx = tid; idx < BK * BN; idx += 256) {
            int r = idx / BN, c = idx % BN;
            Bs[r][c] = Bw[(size_t)(k0 + r) * Nc + cb + c];
        }
        __syncthreads();
        #pragma unroll
        for (int k = 0; k < BK; k++) {
            float a[TM], b[TN];
            #pragma unroll
            for (int i = 0; i < TM; i++) a[i] = As[k][tr * TM + i];
            #pragma unroll
            for (int j = 0; j < TN; j++) b[j] = Bs[k][tc * TN + j];
            #pragma unroll
            for (int i = 0; i < TM; i++)
                #pragma unroll
                for (int j = 0; j < TN; j++) acc[i][j] += a[i] * b[j];
        }
        __syncthreads();
    }
    #pragma unroll
    for (int i = 0; i < TM; i++) {
        int gr = rb + tr * TM + i;
        if (gr < M) {
            #pragma unroll
            for (int j = 0; j < TN; j++)
                C[(size_t)gr * Nc + cb + tc * TN + j] = acc[i][j];
        }
    }
}

// aggregation, Hout = 256: warp per node, weights precomputed in g_simp
__global__ void agg256_kernel(const float* __restrict__ z, float* __restrict__ out, int act) {
    int n = (blockIdx.x * blockDim.x + threadIdx.x) >> 5;
    int lane = threadIdx.x & 31;
    if (n >= NNODES) return;
    const float4* zr = (const float4*)(z + (size_t)n * 256);
    float ws = g_wself[n];
    float4 a0 = zr[lane], a1 = zr[32 + lane];
    a0.x *= ws; a0.y *= ws; a0.z *= ws; a0.w *= ws;
    a1.x *= ws; a1.y *= ws; a1.z *= ws; a1.w *= ws;
    int s1 = g_rowptr[n + 1];
    for (int i = g_rowptr[n]; i < s1; ++i) {
        float w = g_simp[i];
        if (w == 0.f) continue;
        const float4* zc = (const float4*)(z + (size_t)g_colp[i] * 256);
        float4 b0 = zc[lane], b1 = zc[32 + lane];
        a0.x += w * b0.x; a0.y += w * b0.y; a0.z += w * b0.z; a0.w += w * b0.w;
        a1.x += w * b1.x; a1.y += w * b1.y; a1.z += w * b1.z; a1.w += w * b1.w;
    }
    if (act) {
        a0.x = a0.x > 0.f ? a0.x : 0.01f * a0.x;
        a0.y = a0.y > 0.f ? a0.y : 0.01f * a0.y;
        a0.z = a0.z > 0.f ? a0.z : 0.01f * a0.z;
        a0.w = a0.w > 0.f ? a0.w : 0.01f * a0.w;
        a1.x = a1.x > 0.f ? a1.x : 0.01f * a1.x;
        a1.y = a1.y > 0.f ? a1.y : 0.01f * a1.y;
        a1.z = a1.z > 0.f ? a1.z : 0.01f * a1.z;
        a1.w = a1.w > 0.f ? a1.w : 0.01f * a1.w;
    }
    float4* o = (float4*)(out + (size_t)n * 256);
    o[lane] = a0; o[32 + lane] = a1;
}

// aggregation, Hout = 16 (final layer, no activation), weights precomputed
__global__ void agg16_kernel(const float* __restrict__ z, float* __restrict__ out) {
    int n = (blockIdx.x * blockDim.x + threadIdx.x) >> 5;
    int lane = threadIdx.x & 31;
    if (n >= NNODES || lane >= 16) return;
    float acc = g_wself[n] * z[(size_t)n * 16 + lane];
    int s1 = g_rowptr[n + 1];
    for (int i = g_rowptr[n]; i < s1; ++i) {
        float w = g_simp[i];
        if (w == 0.f) continue;
        acc += w * z[(size_t)g_colp[i] * 16 + lane];
    }
    out[(size_t)n * 16 + lane] = acc;
}

// ---------------- host side (single stream, serial) ----------------
static void run_layer(const float* xin, int D, const float* W, int HIDp, int Hout,
                      float* outp, bool act, float* zp, float* Bdev) {
    repack_kernel<<<(D * Hout + 255) / 256, 256>>>(W, D, Hout, HIDp);
    invn_kernel<<<(NNODES + 7) / 8, 256>>>(xin, D);
    sim_fused_kernel<<<(NNODES + 7) / 8, 256>>>(xin, D);
    if (Hout == 256) {
        dim3 grid(4, (NNODES + 127) / 128);
        mma_gemm_kernel<<<grid, 256>>>(xin, Bdev, zp, NNODES, D, 256);
        agg256_kernel<<<(NNODES + 7) / 8, 256>>>(zp, outp, act ? 1 : 0);
    } else {
        dim3 grid(1, (NNODES + 63) / 64);
        sgemm_kernel<64, 16, 16, 4, 1><<<grid, 256>>>(xin, Bdev, zp, NNODES, D, 16);
        agg16_kernel<<<(NNODES + 7) / 8, 256>>>(zp, outp);
    }
}

extern "C" void kernel_launch(void* const* d_in, const int* in_sizes, int n_in,
                              void* d_out, int out_size) {
    const float* x  = (const float*)d_in[0];
    const float* W0 = (const float*)d_in[1];
    const float* W1 = (const float*)d_in[2];
    const float* W2 = (const float*)d_in[3];
    const int*   row = (const int*)d_in[4];
    const int*   col = (const int*)d_in[5];
    float* out = (float*)d_out;

    float *zp, *h1p, *h2p, *Bdev;
    cudaGetSymbolAddress((void**)&zp,  g_z);
    cudaGetSymbolAddress((void**)&h1p, g_h1);
    cudaGetSymbolAddress((void**)&h2p, g_h2);
    cudaGetSymbolAddress((void**)&Bdev, g_B);

    // CSR build (recomputed every call; deterministic work)
    zero_cnt_kernel<<<(NNODES + 255) / 256, 256>>>();
    hist_kernel<<<(NEDGES + 255) / 256, 256>>>(row);
    scan_kernel<<<1, 1024>>>();
    scatter_kernel<<<(NEDGES + 255) / 256, 256>>>(row, col);

    // layer 0: D=128, W0[4,128,64] -> h1[N,256], leaky relu
    run_layer(x,   128, W0, 64, 256, h1p, true,  zp, Bdev);
    // layer 1: D=256, W1[4,256,64] -> h2[N,256], leaky relu
    run_layer(h1p, 256, W1, 64, 256, h2p, true,  zp, Bdev);
    // layer 2: D=256, W2[1,256,16] -> out[N,16], no activation
    run_layer(h2p, 256, W2, 16, 16,  out, false, zp, Bdev);
}

// round 6
// speedup vs baseline: 1.5417x; 1.5417x over previous
#include <cuda_runtime.h>
#include <math.h>

#define NNODES 50000
#define NEDGES 800000

// ---------------- scratch (device globals: allocation-free) ----------------
__device__ int   g_cnt[NNODES];
__device__ int   g_cursor[NNODES];
__device__ int   g_rowptr[NNODES + 1];
__device__ int   g_colp[NEDGES];
__device__ float g_simp[NEDGES];
__device__ float g_invn[NNODES];
__device__ float g_invrs[NNODES];
__device__ float g_wself[NNODES];
__device__ float g_z [NNODES * 256];
__device__ float g_h1[NNODES * 256];
__device__ float g_h2[NNODES * 256];
__device__ float g_B [256 * 256];

// ---------------- CSR build ----------------
__global__ void zero_cnt_kernel() {
    int i = blockIdx.x * blockDim.x + threadIdx.x;
    if (i < NNODES) g_cnt[i] = 0;
}

__global__ void hist_kernel(const int* __restrict__ row) {
    int e = blockIdx.x * blockDim.x + threadIdx.x;
    if (e < NEDGES) atomicAdd(&g_cnt[row[e]], 1);
}

__global__ void scan_kernel() {
    __shared__ int wsum[32];
    __shared__ int carry;
    int tid = threadIdx.x, lane = tid & 31, wid = tid >> 5;
    if (tid == 0) { carry = 0; g_rowptr[0] = 0; }
    __syncthreads();
    for (int base = 0; base < NNODES; base += 1024) {
        int i = base + tid;
        int v = (i < NNODES) ? g_cnt[i] : 0;
        int s = v;
        #pragma unroll
        for (int o = 1; o < 32; o <<= 1) {
            int t = __shfl_up_sync(0xffffffffu, s, o);
            if (lane >= o) s += t;
        }
        if (lane == 31) wsum[wid] = s;
        __syncthreads();
        if (wid == 0) {
            int ws = wsum[lane];
            #pragma unroll
            for (int o = 1; o < 32; o <<= 1) {
                int t = __shfl_up_sync(0xffffffffu, ws, o);
                if (lane >= o) ws += t;
            }
            wsum[lane] = ws;
        }
        __syncthreads();
        int incl = s + (wid ? wsum[wid - 1] : 0) + carry;
        if (i < NNODES) { g_rowptr[i + 1] = incl; g_cursor[i] = incl - v; }
        __syncthreads();
        if (tid == 1023) carry = incl;
        __syncthreads();
    }
}

__global__ void scatter_kernel(const int* __restrict__ row, const int* __restrict__ col) {
    int e = blockIdx.x * blockDim.x + threadIdx.x;
    if (e >= NEDGES) return;
    int r = row[e];
    int pos = atomicAdd(&g_cursor[r], 1);
    g_colp[pos] = col[e];
}

// ---------------- per-layer kernels ----------------
// repack W[h, d, o] -> B[d, h*HID+o]  (dense [D x Hout] row-major)
__global__ void repack_kernel(const float* __restrict__ W, int D, int Hout, int HIDp) {
    int idx = blockIdx.x * blockDim.x + threadIdx.x;
    if (idx >= D * Hout) return;
    int d = idx / Hout, c = idx % Hout;
    int h = c / HIDp, o = c % HIDp;
    g_B[idx] = W[((size_t)h * D + d) * HIDp + o];
}

// 1 / max(||x_n||, 1e-12), warp per node
__global__ void invn_kernel(const float* __restrict__ x, int D) {
    int n = (blockIdx.x * blockDim.x + threadIdx.x) >> 5;
    int lane = threadIdx.x & 31;
    if (n >= NNODES) return;
    const float4* xr = (const float4*)(x + (size_t)n * D);
    int nq = D >> 2;
    float s = 0.f;
    for (int j = lane; j < nq; j += 32) {
        float4 a = xr[j];
        s += a.x * a.x + a.y * a.y + a.z * a.z + a.w * a.w;
    }
    #pragma unroll
    for (int o = 16; o; o >>= 1) s += __shfl_xor_sync(0xffffffffu, s, o);
    if (lane == 0) g_invn[n] = 1.f / fmaxf(sqrtf(s), 1e-12f);
}

// row-stationary thresholded cosine sim: warp per node, row vector lives in
// registers, only the col vector is gathered (halves sim L2 traffic).
__global__ void sim_row_kernel(const float* __restrict__ x, int D) {
    int n = (blockIdx.x * blockDim.x + threadIdx.x) >> 5;
    int lane = threadIdx.x & 31;
    if (n >= NNODES) return;
    const float4* xr = (const float4*)(x + (size_t)n * D);
    float4 r0 = xr[lane];
    float4 r1 = make_float4(0.f, 0.f, 0.f, 0.f);
    if (D == 256) r1 = xr[32 + lane];
    float invn_n = g_invn[n];
    int i1 = g_rowptr[n + 1];
    for (int i = g_rowptr[n]; i < i1; ++i) {
        int c = g_colp[i];
        const float4* xc = (const float4*)(x + (size_t)c * D);
        float4 b0 = xc[lane];
        float s = r0.x * b0.x + r0.y * b0.y + r0.z * b0.z + r0.w * b0.w;
        if (D == 256) {
            float4 b1 = xc[32 + lane];
            s += r1.x * b1.x + r1.y * b1.y + r1.z * b1.z + r1.w * b1.w;
        }
        #pragma unroll
        for (int o = 16; o; o >>= 1) s += __shfl_xor_sync(0xffffffffu, s, o);
        if (lane == 0) {
            s *= invn_n * g_invn[c];
            g_simp[i] = (s < 0.1f) ? 0.f : s;
        }
    }
}

// rowsum / degree / self weight, warp per node
__global__ void rownorm_kernel() {
    int n = (blockIdx.x * blockDim.x + threadIdx.x) >> 5;
    int lane = threadIdx.x & 31;
    if (n >= NNODES) return;
    int s0 = g_rowptr[n], s1 = g_rowptr[n + 1];
    float sum = 0.f;
    int cnt = 0;
    for (int i = s0 + lane; i < s1; i += 32) {
        float v = g_simp[i];
        sum += v;                 // v >= 0 (thresholded cosine), so |v| == v
        cnt += (v != 0.f);
    }
    #pragma unroll
    for (int o = 16; o; o >>= 1) {
        sum += __shfl_xor_sync(0xffffffffu, sum, o);
        cnt += __shfl_xor_sync(0xffffffffu, cnt, o);
    }
    if (lane == 0) {
        g_invrs[n] = (sum > 0.f) ? 1.f / sum : 0.f;
        g_wself[n] = expf(1.f / ((float)cnt + 1.f));
    }
}

// ---------------- 3xTF32 tensor-core GEMM (fp32-accurate) ----------------
__device__ __forceinline__ unsigned f2tf32(float f) {
    unsigned r;
    asm("cvt.rna.tf32.f32 %0, %1;" : "=r"(r) : "f"(f));
    return r;
}

__device__ __forceinline__ void mma_tf32(float c[4], unsigned a0, unsigned a1,
                                         unsigned a2, unsigned a3,
                                         unsigned b0, unsigned b1) {
    asm volatile(
        "mma.sync.aligned.m16n8k8.row.col.f32.tf32.tf32.f32 "
        "{%0,%1,%2,%3}, {%4,%5,%6,%7}, {%8,%9}, {%0,%1,%2,%3};"
        : "+f"(c[0]), "+f"(c[1]), "+f"(c[2]), "+f"(c[3])
        : "r"(a0), "r"(a1), "r"(a2), "r"(a3), "r"(b0), "r"(b1));
}

// C[M, Nc] = A[M, K] * B[K, Nc], BM=128 BN=64 BK=16, 8 warps (warp tile 32x32)
__global__ void __launch_bounds__(256)
mma_gemm_kernel(const float* __restrict__ A, const float* __restrict__ Bw,
                float* __restrict__ C, int M, int K, int Nc) {
    __shared__ unsigned AsHi[128][20];
    __shared__ unsigned AsLo[128][20];
    __shared__ unsigned BsHi[16][68];
    __shared__ unsigned BsLo[16][68];

    int tid = threadIdx.x;
    int lane = tid & 31, w = tid >> 5;
    int wm = w & 3, wn = w >> 2;       // 4 warps in M, 2 in N
    int g = lane >> 2, t = lane & 3;
    int rb = blockIdx.y * 128, cb = blockIdx.x * 64;

    float acc[2][4][4];
    #pragma unroll
    for (int mi = 0; mi < 2; mi++)
        #pragma unroll
        for (int ni = 0; ni < 4; ni++)
            #pragma unroll
            for (int j = 0; j < 4; j++) acc[mi][ni][j] = 0.f;

    for (int k0 = 0; k0 < K; k0 += 16) {
        // A tile 128x16 -> 512 float4, 2 per thread
        #pragma unroll
        for (int f = tid; f < 512; f += 256) {
            int r = f >> 2, kq = f & 3;
            int gr = rb + r;
            float4 v = make_float4(0.f, 0.f, 0.f, 0.f);
            if (gr < M) v = *(const float4*)&A[(size_t)gr * K + k0 + kq * 4];
            float vv[4] = {v.x, v.y, v.z, v.w};
            #pragma unroll
            for (int j = 0; j < 4; j++) {
                unsigned hi = f2tf32(vv[j]);
                AsHi[r][kq * 4 + j] = hi;
                AsLo[r][kq * 4 + j] = f2tf32(vv[j] - __uint_as_float(hi));
            }
        }
        // B tile 16x64 -> 256 float4, 1 per thread
        {
            int r = tid >> 4, nq = tid & 15;
            float4 v = *(const float4*)&Bw[(size_t)(k0 + r) * Nc + cb + nq * 4];
            float vv[4] = {v.x, v.y, v.z, v.w};
            #pragma unroll
            for (int j = 0; j < 4; j++) {
                unsigned hi = f2tf32(vv[j]);
                BsHi[r][nq * 4 + j] = hi;
                BsLo[r][nq * 4 + j] = f2tf32(vv[j] - __uint_as_float(hi));
            }
        }
        __syncthreads();

        #pragma unroll
        for (int kk = 0; kk < 16; kk += 8) {
            unsigned ah[2][4], al[2][4], bh[4][2], bl[4][2];
            #pragma unroll
            for (int mi = 0; mi < 2; mi++) {
                int r0 = wm * 32 + mi * 16 + g;
                ah[mi][0] = AsHi[r0][kk + t];     ah[mi][1] = AsHi[r0 + 8][kk + t];
                ah[mi][2] = AsHi[r0][kk + t + 4]; ah[mi][3] = AsHi[r0 + 8][kk + t + 4];
                al[mi][0] = AsLo[r0][kk + t];     al[mi][1] = AsLo[r0 + 8][kk + t];
                al[mi][2] = AsLo[r0][kk + t + 4]; al[mi][3] = AsLo[r0 + 8][kk + t + 4];
            }
            #pragma unroll
            for (int ni = 0; ni < 4; ni++) {
                int c0 = wn * 32 + ni * 8 + g;
                bh[ni][0] = BsHi[kk + t][c0]; bh[ni][1] = BsHi[kk + t + 4][c0];
                bl[ni][0] = BsLo[kk + t][c0]; bl[ni][1] = BsLo[kk + t + 4][c0];
            }
            #pragma unroll
            for (int mi = 0; mi < 2; mi++)
                #pragma unroll
                for (int ni = 0; ni < 4; ni++) {
                    // 3xTF32: hi*hi + hi*lo + lo*hi ~= fp32 product
                    mma_tf32(acc[mi][ni], ah[mi][0], ah[mi][1], ah[mi][2], ah[mi][3],
                             bh[ni][0], bh[ni][1]);
                    mma_tf32(acc[mi][ni], ah[mi][0], ah[mi][1], ah[mi][2], ah[mi][3],
                             bl[ni][0], bl[ni][1]);
                    mma_tf32(acc[mi][ni], al[mi][0], al[mi][1], al[mi][2], al[mi][3],
                             bh[ni][0], bh[ni][1]);
                }
        }
        __syncthreads();
    }

    #pragma unroll
    for (int mi = 0; mi < 2; mi++) {
        int row = rb + wm * 32 + mi * 16 + g;
        #pragma unroll
        for (int ni = 0; ni < 4; ni++) {
            int colc = cb + wn * 32 + ni * 8 + 2 * t;
            if (row < M)
                *(float2*)&C[(size_t)row * Nc + colc] =
                    make_float2(acc[mi][ni][0], acc[mi][ni][1]);
            if (row + 8 < M)
                *(float2*)&C[(size_t)(row + 8) * Nc + colc] =
                    make_float2(acc[mi][ni][2], acc[mi][ni][3]);
        }
    }
}

// plain tiled SGEMM (kept for the tiny N=16 final projection)
template <int BM, int BN, int BK, int TM, int TN>
__global__ void __launch_bounds__(256)
sgemm_kernel(const float* __restrict__ A, const float* __restrict__ Bw,
             float* __restrict__ C, int M, int K, int Nc) {
    static_assert((BM / TM) * (BN / TN) == 256, "grid of 256 threads");
    __shared__ float As[BK][BM + 4];
    __shared__ float Bs[BK][BN];
    constexpr int TCOLS = BN / TN;
    int tid = threadIdx.x;
    int tr = tid / TCOLS, tc = tid % TCOLS;
    int rb = blockIdx.y * BM, cb = blockIdx.x * BN;
    float acc[TM][TN];
    #pragma unroll
    for (int i = 0; i < TM; i++)
        #pragma unroll
        for (int j = 0; j < TN; j++) acc[i][j] = 0.f;

    for (int k0 = 0; k0 < K; k0 += BK) {
        for (int idx = tid; idx < BM * BK; idx += 256) {
            int r = idx / BK, c = idx % BK;
            int gr = rb + r;
            As[c][r] = (gr < M) ? A[(size_t)gr * K + k0 + c] : 0.f;
        }
        for (int idx = tid; idx < BK * BN; idx += 256) {
            int r = idx / BN, c = idx % BN;
            Bs[r][c] = Bw[(size_t)(k0 + r) * Nc + cb + c];
        }
        __syncthreads();
        #pragma unroll
        for (int k = 0; k < BK; k++) {
            float a[TM], b[TN];
            #pragma unroll
            for (int i = 0; i < TM; i++) a[i] = As[k][tr * TM + i];
            #pragma unroll
            for (int j = 0; j < TN; j++) b[j] = Bs[k][tc * TN + j];
            #pragma unroll
            for (int i = 0; i < TM; i++)
                #pragma unroll
                for (int j = 0; j < TN; j++) acc[i][j] += a[i] * b[j];
        }
        __syncthreads();
    }
    #pragma unroll
    for (int i = 0; i < TM; i++) {
        int gr = rb + tr * TM + i;
        if (gr < M) {
            #pragma unroll
            for (int j = 0; j < TN; j++)
                C[(size_t)gr * Nc + cb + tc * TN + j] = acc[i][j];
        }
    }
}

// aggregation, Hout = 256: warp per node, lane owns 4+4 contiguous cols
__global__ void agg256_kernel(const float* __restrict__ z, float* __restrict__ out, int act) {
    int n = (blockIdx.x * blockDim.x + threadIdx.x) >> 5;
    int lane = threadIdx.x & 31;
    if (n >= NNODES) return;
    const float4* zr = (const float4*)(z + (size_t)n * 256);
    float ws = g_wself[n];
    float4 a0 = zr[lane], a1 = zr[32 + lane];
    a0.x *= ws; a0.y *= ws; a0.z *= ws; a0.w *= ws;
    a1.x *= ws; a1.y *= ws; a1.z *= ws; a1.w *= ws;
    float irs = g_invrs[n];
    int s1 = g_rowptr[n + 1];
    for (int i = g_rowptr[n]; i < s1; ++i) {
        float sv = g_simp[i];
        if (sv == 0.f) continue;
        float w = expf(sv * irs);
        const float4* zc = (const float4*)(z + (size_t)g_colp[i] * 256);
        float4 b0 = zc[lane], b1 = zc[32 + lane];
        a0.x += w * b0.x; a0.y += w * b0.y; a0.z += w * b0.z; a0.w += w * b0.w;
        a1.x += w * b1.x; a1.y += w * b1.y; a1.z += w * b1.z; a1.w += w * b1.w;
    }
    if (act) {
        a0.x = a0.x > 0.f ? a0.x : 0.01f * a0.x;
        a0.y = a0.y > 0.f ? a0.y : 0.01f * a0.y;
        a0.z = a0.z > 0.f ? a0.z : 0.01f * a0.z;
        a0.w = a0.w > 0.f ? a0.w : 0.01f * a0.w;
        a1.x = a1.x > 0.f ? a1.x : 0.01f * a1.x;
        a1.y = a1.y > 0.f ? a1.y : 0.01f * a1.y;
        a1.z = a1.z > 0.f ? a1.z : 0.01f * a1.z;
        a1.w = a1.w > 0.f ? a1.w : 0.01f * a1.w;
    }
    float4* o = (float4*)(out + (size_t)n * 256);
    o[lane] = a0; o[32 + lane] = a1;
}

// aggregation, Hout = 16 (final layer, no activation)
__global__ void agg16_kernel(const float* __restrict__ z, float* __restrict__ out) {
    int n = (blockIdx.x * blockDim.x + threadIdx.x) >> 5;
    int lane = threadIdx.x & 31;
    if (n >= NNODES || lane >= 16) return;
    float acc = g_wself[n] * z[(size_t)n * 16 + lane];
    float irs = g_invrs[n];
    int s1 = g_rowptr[n + 1];
    for (int i = g_rowptr[n]; i < s1; ++i) {
        float sv = g_simp[i];
        if (sv == 0.f) continue;
        acc += expf(sv * irs) * z[(size_t)g_colp[i] * 16 + lane];
    }
    out[(size_t)n * 16 + lane] = acc;
}

// ---------------- host side ----------------
static void run_layer(const float* xin, int D, const float* W, int HIDp, int Hout,
                      float* outp, bool act, float* zp) {
    repack_kernel<<<(D * Hout + 255) / 256, 256>>>(W, D, Hout, HIDp);
    invn_kernel<<<(NNODES + 7) / 8, 256>>>(xin, D);
    sim_row_kernel<<<(NNODES + 7) / 8, 256>>>(xin, D);
    rownorm_kernel<<<(NNODES + 7) / 8, 256>>>();
    float* Bdev;
    cudaGetSymbolAddress((void**)&Bdev, g_B);
    if (Hout == 256) {
        dim3 grid(256 / 64, (NNODES + 127) / 128);
        mma_gemm_kernel<<<grid, 256>>>(xin, Bdev, zp, NNODES, D, 256);
        agg256_kernel<<<(NNODES + 7) / 8, 256>>>(zp, outp, act ? 1 : 0);
    } else {
        dim3 grid(1, (NNODES + 63) / 64);
        sgemm_kernel<64, 16, 16, 4, 1><<<grid, 256>>>(xin, Bdev, zp, NNODES, D, 16);
        agg16_kernel<<<(NNODES + 7) / 8, 256>>>(zp, outp);
    }
}

extern "C" void kernel_launch(void* const* d_in, const int* in_sizes, int n_in,
                              void* d_out, int out_size) {
    const float* x  = (const float*)d_in[0];
    const float* W0 = (const float*)d_in[1];
    const float* W1 = (const float*)d_in[2];
    const float* W2 = (const float*)d_in[3];
    const int*   row = (const int*)d_in[4];
    const int*   col = (const int*)d_in[5];
    float* out = (float*)d_out;

    float *zp, *h1p, *h2p;
    cudaGetSymbolAddress((void**)&zp,  g_z);
    cudaGetSymbolAddress((void**)&h1p, g_h1);
    cudaGetSymbolAddress((void**)&h2p, g_h2);

    // CSR build (recomputed every call; deterministic work)
    zero_cnt_kernel<<<(NNODES + 255) / 256, 256>>>();
    hist_kernel<<<(NEDGES + 255) / 256, 256>>>(row);
    scan_kernel<<<1, 1024>>>();
    scatter_kernel<<<(NEDGES + 255) / 256, 256>>>(row, col);

    // layer 0: D=128, W0[4,128,64] -> h1[N,256], leaky relu
    run_layer(x,   128, W0, 64, 256, h1p, true,  zp);
    // layer 1: D=256, W1[4,256,64] -> h2[N,256], leaky relu
    run_layer(h1p, 256, W1, 64, 256, h2p, true,  zp);
    // layer 2: D=256, W2[1,256,16] -> out[N,16], no activation
    run_layer(h2p, 256, W2, 16, 16,  out, false, zp);
}